// round 1
// baseline (speedup 1.0000x reference)
#include <cuda_runtime.h>
#include <cstdint>

// ---------------------------------------------------------------------------
// FlexibleWaveConv2d: 2-level Haar DWT -> 4 per-position [32x128]x[128x128]
// GEMMs against bilinearly upsampled (16x16 -> 32x32) weights -> IDWT x2.
//
// Pipeline (4 kernels):
//   K1a k_dwt  : x(32,128,128,128) -> A[s][pos][k=i][b]  (4x4 block Haar, tf32-rna)
//   K1b k_wprep: w_s(i,o,16,16)    -> Wt[s][uv][k=i][o]  (transpose, tf32-rna)
//   K2  k_gemm : per (s,pos): Wint = bilinear(taps) in smem (rna), A in smem,
//                tf32 mma.sync m16n8k8 -> C[s][pos][b][o]
//   K3  k_idwt : C -> out via idwt + zero-idwt (4x4 broadcast, +/- patterns)
// ---------------------------------------------------------------------------

#define S_A   (1024L*128*32)       // per-subband stride in g_A
#define N_A   (4L*1024*128*32)
#define N_WT  (4L*256*128*128)
#define N_C   (4L*1024*32*128)

static __device__ float g_A [N_A];   // [s][pos][k][b]
static __device__ float g_Wt[N_WT];  // [s][u*16+v][k][o]
static __device__ float g_C [N_C];   // [s][pos][b][o]

__device__ __forceinline__ float rna_tf32(float x) {
    float r;
    asm("cvt.rna.tf32.f32 %0, %1;" : "=f"(r) : "f"(x));
    return r;
}

// jax.image.resize bilinear, 16 -> 32, antialias irrelevant for upsampling.
// sample(j) = j/2 - 0.25 ; boundary weights renormalized -> single tap.
__device__ __forceinline__ void taps(int j, int& i0, int& i1, float& c0, float& c1) {
    if (j == 0)        { i0 = 0;  i1 = 0;  c0 = 1.0f;  c1 = 0.0f; }
    else if (j == 31)  { i0 = 15; i1 = 15; c0 = 1.0f;  c1 = 0.0f; }
    else if (j & 1)    { int k = j >> 1; i0 = k;     i1 = k + 1; c0 = 0.75f; c1 = 0.25f; }
    else               { int k = j >> 1; i0 = k - 1; i1 = k;     c0 = 0.25f; c1 = 0.75f; }
}

// ---------------------------------------------------------------------------
// K1a: 4x4 block Haar. grid (32 x-rows, 128 channels), block 1024.
// ---------------------------------------------------------------------------
__global__ __launch_bounds__(1024) void k_dwt(const float* __restrict__ x) {
    const int xr = blockIdx.x;   // 0..31
    const int ci = blockIdx.y;   // 0..127
    __shared__ float vals[4][32][33];

    const int tid = threadIdx.x;
    {
        const int b = tid >> 5, y = tid & 31;
        const float4* px = reinterpret_cast<const float4*>(x)
                         + ((long)(b * 128 + ci) * 128 + 4 * xr) * 32 + y;
        float4 r0 = px[0], r1 = px[32], r2 = px[64], r3 = px[96];
        float q00 = r0.x + r0.y + r1.x + r1.y;   // rows 0-1, cols 0-1
        float q01 = r0.z + r0.w + r1.z + r1.w;   // rows 0-1, cols 2-3
        float q10 = r2.x + r2.y + r3.x + r3.y;   // rows 2-3, cols 0-1
        float q11 = r2.z + r2.w + r3.z + r3.w;   // rows 2-3, cols 2-3
        vals[0][y][b] = rna_tf32(0.25f * (q00 + q01 + q10 + q11));  // ll
        vals[1][y][b] = rna_tf32(0.25f * (q00 - q01 + q10 - q11));  // lh (col sign)
        vals[2][y][b] = rna_tf32(0.25f * (q00 + q01 - q10 - q11));  // hl (row sign)
        vals[3][y][b] = rna_tf32(0.25f * (q00 - q01 - q10 + q11));  // hh
    }
    __syncthreads();
    {
        const int y2 = tid >> 5, b2 = tid & 31;
        const long base = ((long)(xr * 32 + y2) * 128 + ci) * 32 + b2;
        g_A[0 * S_A + base] = vals[0][y2][b2];
        g_A[1 * S_A + base] = vals[1][y2][b2];
        g_A[2 * S_A + base] = vals[2][y2][b2];
        g_A[3 * S_A + base] = vals[3][y2][b2];
    }
}

// ---------------------------------------------------------------------------
// K1b: weight transpose (i,o,u,v) -> [s][uv][k][o], tf32-rna.
// grid (8 uv-blocks, 128 k, 4 s), block 256.
// ---------------------------------------------------------------------------
__global__ __launch_bounds__(256) void k_wprep(const float* __restrict__ w0,
                                               const float* __restrict__ w1,
                                               const float* __restrict__ w2,
                                               const float* __restrict__ w3) {
    const int uvb = blockIdx.x, k = blockIdx.y, s = blockIdx.z;
    const float* w = (s == 0) ? w0 : (s == 1) ? w1 : (s == 2) ? w2 : w3;
    __shared__ float t[128][33];
    const int tid = threadIdx.x;
    const int uvl = tid & 31;
    const int uv0 = uvb * 32;
    for (int o = tid >> 5; o < 128; o += 8)
        t[o][uvl] = w[((long)k * 128 + o) * 256 + uv0 + uvl];
    __syncthreads();
    const int o = tid & 127;
    for (int j = tid >> 7; j < 32; j += 2)
        g_Wt[(((long)s * 256 + uv0 + j) * 128 + k) * 128 + o] = rna_tf32(t[o][j]);
}

// ---------------------------------------------------------------------------
// K2: per-(subband, position) GEMM, tf32 mma.sync m16n8k8.
// grid (1024 pos, 4 s), block 256 (8 warps, warp -> 16 output cols).
// dyn smem: sA[128][36] + sW[128][128] = 83968 B.
// ---------------------------------------------------------------------------
#define K2_SMEM ((128 * 36 + 128 * 128) * 4)

__device__ __forceinline__ void mma_tf32(float acc[4], const uint32_t a[4],
                                         const uint32_t b[2]) {
    asm volatile(
        "mma.sync.aligned.m16n8k8.row.col.f32.tf32.tf32.f32 "
        "{%0,%1,%2,%3}, {%4,%5,%6,%7}, {%8,%9}, {%0,%1,%2,%3};\n"
        : "+f"(acc[0]), "+f"(acc[1]), "+f"(acc[2]), "+f"(acc[3])
        : "r"(a[0]), "r"(a[1]), "r"(a[2]), "r"(a[3]), "r"(b[0]), "r"(b[1]));
}

__global__ __launch_bounds__(256) void k_gemm() {
    extern __shared__ float sm[];
    float* sA = sm;               // [k][b] stride 36
    float* sW = sm + 128 * 36;    // [k][o] stride 128

    const int pos = blockIdx.x, s = blockIdx.y;
    const int xr = pos >> 5, yc = pos & 31;
    const int tid = threadIdx.x;

    // stage A[s][pos] (128k x 32b, contiguous) into smem with pad-36 rows
    const float4* Ag = reinterpret_cast<const float4*>(g_A + ((long)s * 1024 + pos) * 4096);
    for (int idx = tid; idx < 1024; idx += 256) {
        const int k = idx >> 3, b4 = (idx & 7) << 2;
        *reinterpret_cast<float4*>(&sA[k * 36 + b4]) = Ag[idx];
    }

    // build Wint = bilinear(4 taps) -> smem, re-round to tf32 (unbiased)
    int u0, u1, v0, v1; float cu0, cu1, cv0, cv1;
    taps(xr, u0, u1, cu0, cu1);
    taps(yc, v0, v1, cv0, cv1);
    const float4* t00 = (const float4*)(g_Wt + ((long)s * 256 + u0 * 16 + v0) * 16384);
    const float4* t01 = (const float4*)(g_Wt + ((long)s * 256 + u0 * 16 + v1) * 16384);
    const float4* t10 = (const float4*)(g_Wt + ((long)s * 256 + u1 * 16 + v0) * 16384);
    const float4* t11 = (const float4*)(g_Wt + ((long)s * 256 + u1 * 16 + v1) * 16384);
    const float c00 = cu0 * cv0, c01 = cu0 * cv1, c10 = cu1 * cv0, c11 = cu1 * cv1;
    for (int idx = tid; idx < 4096; idx += 256) {
        float4 a = t00[idx], b = t01[idx], c = t10[idx], d = t11[idx];
        float4 r;
        r.x = rna_tf32(c00 * a.x + c01 * b.x + c10 * c.x + c11 * d.x);
        r.y = rna_tf32(c00 * a.y + c01 * b.y + c10 * c.y + c11 * d.y);
        r.z = rna_tf32(c00 * a.z + c01 * b.z + c10 * c.z + c11 * d.z);
        r.w = rna_tf32(c00 * a.w + c01 * b.w + c10 * c.w + c11 * d.w);
        reinterpret_cast<float4*>(sW)[idx] = r;
    }
    __syncthreads();

    const int warp = tid >> 5, lane = tid & 31;
    const int g = lane >> 2, q = lane & 3;
    const int ob = warp << 4;                 // 16 output cols per warp

    float acc[2][2][4];
#pragma unroll
    for (int m = 0; m < 2; m++)
#pragma unroll
        for (int n = 0; n < 2; n++)
#pragma unroll
            for (int i = 0; i < 4; i++) acc[m][n][i] = 0.0f;

#pragma unroll 4
    for (int k0 = 0; k0 < 128; k0 += 8) {
        uint32_t af[2][4];
#pragma unroll
        for (int m = 0; m < 2; m++) {
            const int r0 = m * 16 + g;
            af[m][0] = __float_as_uint(sA[(k0 + q) * 36 + r0]);
            af[m][1] = __float_as_uint(sA[(k0 + q) * 36 + r0 + 8]);
            af[m][2] = __float_as_uint(sA[(k0 + q + 4) * 36 + r0]);
            af[m][3] = __float_as_uint(sA[(k0 + q + 4) * 36 + r0 + 8]);
        }
        uint32_t bf[2][2];
#pragma unroll
        for (int n = 0; n < 2; n++) {
            const int oc = ob + n * 8 + g;
            bf[n][0] = __float_as_uint(sW[(k0 + q) * 128 + oc]);
            bf[n][1] = __float_as_uint(sW[(k0 + q + 4) * 128 + oc]);
        }
#pragma unroll
        for (int m = 0; m < 2; m++)
#pragma unroll
            for (int n = 0; n < 2; n++) mma_tf32(acc[m][n], af[m], bf[n]);
    }

    // store C[s][pos][b][o]
    float* Cb = g_C + ((long)s * 1024 + pos) * 4096;
#pragma unroll
    for (int m = 0; m < 2; m++)
#pragma unroll
        for (int n = 0; n < 2; n++) {
            const int row = m * 16 + g;
            const int col = ob + n * 8 + q * 2;
            *reinterpret_cast<float2*>(&Cb[row * 128 + col]) =
                make_float2(acc[m][n][0], acc[m][n][1]);
            *reinterpret_cast<float2*>(&Cb[(row + 8) * 128 + col]) =
                make_float2(acc[m][n][2], acc[m][n][3]);
        }
}

// ---------------------------------------------------------------------------
// K3: idwt(out_ll,out_lh,out_hl,out_hh) then idwt(.,0,0,0):
//   out[b][o][4x+2p+dh][4y+2r+dw] = 0.25*(ll + (-1)^r lh + (-1)^p hl + (-1)^(p+r) hh)
// grid (32 x, 4 o-groups, 32 b), block 256.
// ---------------------------------------------------------------------------
__global__ __launch_bounds__(256) void k_idwt(float* __restrict__ out) {
    const int xr = blockIdx.x, og = blockIdx.y, b = blockIdx.z;
    __shared__ float sC[4][32][33];
    const int tid = threadIdx.x;

    for (int idx = tid; idx < 4096; idx += 256) {
        const int s = idx >> 10, y = (idx >> 5) & 31, o = idx & 31;
        sC[s][y][o] = g_C[(((long)s * 1024 + xr * 32 + y) * 32 + b) * 128 + og * 32 + o];
    }
    __syncthreads();

    const int w4 = tid & 31;            // y index / float4 column
    const int ph = (tid >> 5) & 3;      // 2p + dh
    const int j0 = tid >> 7;            // 0..1
    const float sp = (ph >> 1) ? -1.0f : 1.0f;
    const int h = 4 * xr + ph;
    const int y = w4;

    for (int j = j0; j < 32; j += 2) {
        const float ll = sC[0][y][j], lh = sC[1][y][j];
        const float hl = sC[2][y][j], hh = sC[3][y][j];
        const float e0 = 0.25f * (ll + lh + sp * (hl + hh));   // r = 0
        const float e1 = 0.25f * (ll - lh + sp * (hl - hh));   // r = 1
        const int oc = og * 32 + j;
        *reinterpret_cast<float4*>(&out[(((long)b * 128 + oc) * 128 + h) * 128 + 4 * w4]) =
            make_float4(e0, e0, e1, e1);
    }
}

// ---------------------------------------------------------------------------
extern "C" void kernel_launch(void* const* d_in, const int* in_sizes, int n_in,
                              void* d_out, int out_size) {
    (void)in_sizes; (void)n_in; (void)out_size;
    const float* x  = (const float*)d_in[0];
    const float* w1 = (const float*)d_in[1];
    const float* w2 = (const float*)d_in[2];
    const float* w3 = (const float*)d_in[3];
    const float* w4 = (const float*)d_in[4];

    cudaFuncSetAttribute(k_gemm, cudaFuncAttributeMaxDynamicSharedMemorySize, K2_SMEM);

    k_dwt  <<<dim3(32, 128), 1024>>>(x);
    k_wprep<<<dim3(8, 128, 4), 256>>>(w1, w2, w3, w4);
    k_gemm <<<dim3(1024, 4), 256, K2_SMEM>>>();
    k_idwt <<<dim3(32, 4, 32), 256>>>((float*)d_out);
}